// round 8
// baseline (speedup 1.0000x reference)
#include <cuda_runtime.h>
#include <cstdint>

#define NN      96
#define GRIDN   9216
#define HIDD    9984
#define OUTD    9600
#define BATCH   256
#define INPD    768
#define KDIM    384
#define HPI     1.5707963267948966f

// Static device scratch for sparse W2.
__device__ int   g_cols[OUTD * 5];
__device__ float g_vals[OUTD * 5];

// ---------------------------------------------------------------------------
// Build sparse W2_dyn: one thread per (row, slot) for latency hiding.
// ---------------------------------------------------------------------------
__global__ void build_w2_kernel(const float* __restrict__ Beta,
                                const float* __restrict__ W2f) {
    int idx = blockIdx.x * 256 + threadIdx.x;
    if (idx >= OUTD * 5) return;
    int r = idx / 5;
    int k = idx - r * 5;
    const float* Br = Beta + (size_t)r * HIDD;
    const float* Fr = W2f  + (size_t)r * HIDD;
    int c; float v;
    if (r < GRIDN) {
        int i = r / NN, j = r % NN;
        switch (k) {
        case 0: c = r; v = Fr[r]; break;
        case 1:
            if (j > 0)      { c = r - 1;            v = Fr[c]; }
            else            { c = GRIDN + 2*NN + i; v = atanf(Br[c]) + HPI; }
            break;
        case 2:
            if (j < NN - 1) { c = r + 1;            v = atanf(Br[c]) + HPI; }
            else            { c = GRIDN + 3*NN + i; v = atanf(Br[c]) + HPI; }
            break;
        case 3:
            if (i > 0)      { c = r - NN;           v = Fr[c]; }
            else            { c = GRIDN + j;        v = atanf(Br[c]) + HPI; }
            break;
        default:
            if (i < NN - 1) { c = r + NN;           v = atanf(Br[c]) + HPI; }
            else            { c = GRIDN + NN + j;   v = atanf(Br[c]) + HPI; }
            break;
        }
    } else {
        int g = r - GRIDN;
        int node;
        if      (g < NN)     node = g;
        else if (g < 2 * NN) node = (NN - 1) * NN + (g - NN);
        else if (g < 3 * NN) node = (g - 2 * NN) * NN;
        else                 node = (g - 3 * NN) * NN + (NN - 1);
        switch (k) {
        case 0:  c = r;        v = Fr[r];        break;
        case 1:  c = node;     v = Fr[node];     break;
        case 2:  c = OUTD + g; v = Fr[OUTD + g]; break;
        default: c = 0;        v = 0.0f;         break;
        }
    }
    g_cols[idx] = c;
    g_vals[idx] = v;
}

// ---------------------------------------------------------------------------
// hid[:, :9216] = x[:, :384] @ W1[:9216, :384]^T  via mma.sync tf32.
// (unchanged from R7: reg double-buffered staging, interleaved K, LDS.64)
// ---------------------------------------------------------------------------
#define KC     32
#define NCHK   (KDIM / KC)
#define PITCH  40

__device__ __forceinline__ uint32_t f2tf32(float f) {
    uint32_t o;
    asm("cvt.rna.tf32.f32 %0, %1;" : "=r"(o) : "f"(f));
    return o;
}

__global__ void __launch_bounds__(256, 1)
gemm_tf32_kernel(const float* __restrict__ X, const float* __restrict__ W1,
                 float* __restrict__ hid) {
    __shared__ uint32_t Xs[128 * PITCH];
    __shared__ uint32_t Ws[128 * PITCH];

    const int t    = threadIdx.x;
    const int wid  = t >> 5;
    const int lane = t & 31;
    const int g    = lane >> 2;
    const int tg   = lane & 3;
    const int wm   = wid >> 2;
    const int wn   = wid & 3;
    const int m0   = blockIdx.y * 128;
    const int n0   = blockIdx.x * 128;

    const float* srcp[4];
    uint32_t*    dstp[4];
#pragma unroll
    for (int i = 0; i < 4; i++) {
        int idx  = t + i * 256;
        int tile = idx >> 9;
        int row  = (idx >> 2) & 127;
        int grp  = idx & 3;
        srcp[i] = (tile ? W1 + (size_t)(n0 + row) * INPD
                        : X  + (size_t)(m0 + row) * INPD) + grp * 8;
        dstp[i] = (tile ? Ws : Xs) + row * PITCH + grp * 8;
    }

    float4 lo[4], hi[4];
#pragma unroll
    for (int i = 0; i < 4; i++) {
        lo[i] = *(const float4*)(srcp[i]);
        hi[i] = *(const float4*)(srcp[i] + 4);
    }

    float c[4][4][4];
#pragma unroll
    for (int mf = 0; mf < 4; mf++)
#pragma unroll
        for (int nf = 0; nf < 4; nf++)
#pragma unroll
            for (int q = 0; q < 4; q++) c[mf][nf][q] = 0.0f;

    for (int kc = 0; kc < NCHK; kc++) {
#pragma unroll
        for (int i = 0; i < 4; i++) {
            uint32_t* d = dstp[i];
            d[0] = f2tf32(lo[i].x); d[1] = f2tf32(hi[i].x);
            d[2] = f2tf32(lo[i].y); d[3] = f2tf32(hi[i].y);
            d[4] = f2tf32(lo[i].z); d[5] = f2tf32(hi[i].z);
            d[6] = f2tf32(lo[i].w); d[7] = f2tf32(hi[i].w);
        }
        __syncthreads();

        if (kc + 1 < NCHK) {
            const int off = (kc + 1) * KC;
#pragma unroll
            for (int i = 0; i < 4; i++) {
                lo[i] = *(const float4*)(srcp[i] + off);
                hi[i] = *(const float4*)(srcp[i] + off + 4);
            }
        }

#pragma unroll
        for (int ks = 0; ks < 4; ks++) {
            const int kb = ks * 8 + tg * 2;
            uint2 a0[4], a1[4], bv[4];
#pragma unroll
            for (int mf = 0; mf < 4; mf++) {
                int row = wm * 64 + mf * 16 + g;
                a0[mf] = *(const uint2*)&Xs[row * PITCH + kb];
                a1[mf] = *(const uint2*)&Xs[(row + 8) * PITCH + kb];
            }
#pragma unroll
            for (int nf = 0; nf < 4; nf++) {
                int col = wn * 32 + nf * 8 + g;
                bv[nf] = *(const uint2*)&Ws[col * PITCH + kb];
            }
#pragma unroll
            for (int mf = 0; mf < 4; mf++)
#pragma unroll
                for (int nf = 0; nf < 4; nf++)
                    asm volatile(
                        "mma.sync.aligned.m16n8k8.row.col.f32.tf32.tf32.f32 "
                        "{%0,%1,%2,%3}, {%4,%5,%6,%7}, {%8,%9}, {%0,%1,%2,%3};"
                        : "+f"(c[mf][nf][0]), "+f"(c[mf][nf][1]),
                          "+f"(c[mf][nf][2]), "+f"(c[mf][nf][3])
                        : "r"(a0[mf].x), "r"(a1[mf].x), "r"(a0[mf].y), "r"(a1[mf].y),
                          "r"(bv[nf].x), "r"(bv[nf].y));
        }
        __syncthreads();
    }

#pragma unroll
    for (int mf = 0; mf < 4; mf++) {
        int row = m0 + wm * 64 + mf * 16 + g;
#pragma unroll
        for (int nf = 0; nf < 4; nf++) {
            int col = n0 + wn * 32 + nf * 8 + tg * 2;
            float2* p0 = (float2*)(hid + (size_t)row * HIDD + col);
            float2* p1 = (float2*)(hid + (size_t)(row + 8) * HIDD + col);
            *p0 = make_float2(c[mf][nf][0], c[mf][nf][1]);
            *p1 = make_float2(c[mf][nf][2], c[mf][nf][3]);
        }
    }
}

// ---------------------------------------------------------------------------
// Fused spmm + hid-tail copy.
//  blockIdx.x < 150 : outp[b, r] = sum_k vals[r,k] * field(b, cols[r,k])
//                     where field reads hid for c < GRIDN, x for c >= GRIDN
//                     (so no dependency on the copy). 64 rows x 64 batches.
//  blockIdx.x == 150: hid[:, 9216:9984] = x for this y-slice of 64 batches.
// ---------------------------------------------------------------------------
__global__ void __launch_bounds__(256)
spmm_fused_kernel(const float* __restrict__ hid, const float* __restrict__ x,
                  float* __restrict__ outp, float* __restrict__ hid_tail_dst) {
    const int t  = threadIdx.x;
    const int by = blockIdx.y;           // 0..3, 64 batches each

    if (blockIdx.x == 150) {             // copy block: x -> hid tail
        // 64 batches * 192 float4 = 12288 float4; 256 threads -> 48 each.
        for (int i = t; i < 64 * 192; i += 256) {
            int b = by * 64 + (i / 192);
            int q = i % 192;
            const float4* src = (const float4*)(x + (size_t)b * INPD);
            float4*       dst = (float4*)(hid_tail_dst + (size_t)b * HIDD + GRIDN);
            dst[q] = src[q];
        }
        return;
    }

    __shared__ int   sc[64 * 5];
    __shared__ float sv[64 * 5];
    const int r0 = blockIdx.x * 64;
    for (int i = t; i < 320; i += 256) {
        sc[i] = g_cols[r0 * 5 + i];
        sv[i] = g_vals[r0 * 5 + i];
    }
    __syncthreads();

    const int rr = t & 63;
    const int bs = t >> 6;               // 0..3
    const int r  = r0 + rr;
    const int bb = by * 64 + bs;         // first batch for this thread

    const float* base[5];
    size_t       strd[5];
    float        val[5];
#pragma unroll
    for (int k = 0; k < 5; k++) {
        int c  = sc[rr * 5 + k];
        val[k] = sv[rr * 5 + k];
        if (c < GRIDN) { base[k] = hid + (size_t)bb * HIDD + c;          strd[k] = 4 * HIDD; }
        else           { base[k] = x   + (size_t)bb * INPD + (c - GRIDN); strd[k] = 4 * INPD; }
    }

    float acc[16];
#pragma unroll
    for (int u = 0; u < 16; u++) acc[u]  = val[0] * base[0][u * strd[0]];
#pragma unroll
    for (int u = 0; u < 16; u++) acc[u] += val[1] * base[1][u * strd[1]];
#pragma unroll
    for (int u = 0; u < 16; u++) acc[u] += val[2] * base[2][u * strd[2]];
#pragma unroll
    for (int u = 0; u < 16; u++) acc[u] += val[3] * base[3][u * strd[3]];
#pragma unroll
    for (int u = 0; u < 16; u++) acc[u] += val[4] * base[4][u * strd[4]];

    float* ob = outp + (size_t)bb * OUTD + r;
#pragma unroll
    for (int u = 0; u < 16; u++) ob[(size_t)u * 4 * OUTD] = acc[u];
}

// ---------------------------------------------------------------------------
extern "C" void kernel_launch(void* const* d_in, const int* in_sizes, int n_in,
                              void* d_out, int out_size) {
    const float* x    = (const float*)d_in[0];
    const float* W1   = (const float*)d_in[1];
    const float* Beta = (const float*)d_in[4];
    const float* W2f  = (const float*)d_in[5];

    if (out_size < BATCH * OUTD + BATCH * HIDD) return;   // layout guard

    float* outp = (float*)d_out;                          // [256, 9600]
    float* hid  = (float*)d_out + (size_t)BATCH * OUTD;   // [256, 9984]

    build_w2_kernel<<<(OUTD * 5 + 255) / 256, 256>>>(Beta, W2f);

    dim3 ggrid(GRIDN / 128, BATCH / 128);   // (72, 2)
    gemm_tf32_kernel<<<ggrid, 256>>>(x, W1, hid);

    dim3 sgrid(151, 4);                     // 150 spmm cols + 1 copy col
    spmm_fused_kernel<<<sgrid, 256>>>(hid, x, outp, hid);
}

// round 9
// speedup vs baseline: 1.1308x; 1.1308x over previous
#include <cuda_runtime.h>
#include <cstdint>

#define NN      96
#define GRIDN   9216
#define HIDD    9984
#define OUTD    9600
#define BATCH   256
#define INPD    768
#define KDIM    384
#define HPI     1.5707963267948966f

// ---------------------------------------------------------------------------
// hid[:, :9216] = x[:, :384] @ W1[:9216, :384]^T  via mma.sync tf32.
// CTA tile M=128 x N=128, K chunks of 32, register double-buffered staging.
// ---------------------------------------------------------------------------
#define KC     32
#define NCHK   (KDIM / KC)
#define PITCH  40

__device__ __forceinline__ uint32_t f2tf32(float f) {
    uint32_t o;
    asm("cvt.rna.tf32.f32 %0, %1;" : "=r"(o) : "f"(f));
    return o;
}

__global__ void __launch_bounds__(256, 1)
gemm_tf32_kernel(const float* __restrict__ X, const float* __restrict__ W1,
                 float* __restrict__ hid) {
    __shared__ uint32_t Xs[128 * PITCH];
    __shared__ uint32_t Ws[128 * PITCH];

    const int t    = threadIdx.x;
    const int wid  = t >> 5;
    const int lane = t & 31;
    const int g    = lane >> 2;
    const int tg   = lane & 3;
    const int wm   = wid >> 2;
    const int wn   = wid & 3;
    const int m0   = blockIdx.y * 128;
    const int n0   = blockIdx.x * 128;

    const float* srcp[4];
    uint32_t*    dstp[4];
#pragma unroll
    for (int i = 0; i < 4; i++) {
        int idx  = t + i * 256;
        int tile = idx >> 9;
        int row  = (idx >> 2) & 127;
        int grp  = idx & 3;
        srcp[i] = (tile ? W1 + (size_t)(n0 + row) * INPD
                        : X  + (size_t)(m0 + row) * INPD) + grp * 8;
        dstp[i] = (tile ? Ws : Xs) + row * PITCH + grp * 8;
    }

    float4 lo[4], hi[4];
#pragma unroll
    for (int i = 0; i < 4; i++) {
        lo[i] = *(const float4*)(srcp[i]);
        hi[i] = *(const float4*)(srcp[i] + 4);
    }

    float c[4][4][4];
#pragma unroll
    for (int mf = 0; mf < 4; mf++)
#pragma unroll
        for (int nf = 0; nf < 4; nf++)
#pragma unroll
            for (int q = 0; q < 4; q++) c[mf][nf][q] = 0.0f;

    for (int kc = 0; kc < NCHK; kc++) {
#pragma unroll
        for (int i = 0; i < 4; i++) {
            uint32_t* d = dstp[i];
            d[0] = f2tf32(lo[i].x); d[1] = f2tf32(hi[i].x);
            d[2] = f2tf32(lo[i].y); d[3] = f2tf32(hi[i].y);
            d[4] = f2tf32(lo[i].z); d[5] = f2tf32(hi[i].z);
            d[6] = f2tf32(lo[i].w); d[7] = f2tf32(hi[i].w);
        }
        __syncthreads();

        if (kc + 1 < NCHK) {
            const int off = (kc + 1) * KC;
#pragma unroll
            for (int i = 0; i < 4; i++) {
                lo[i] = *(const float4*)(srcp[i] + off);
                hi[i] = *(const float4*)(srcp[i] + off + 4);
            }
        }

#pragma unroll
        for (int ks = 0; ks < 4; ks++) {
            const int kb = ks * 8 + tg * 2;
            uint2 a0[4], a1[4], bv[4];
#pragma unroll
            for (int mf = 0; mf < 4; mf++) {
                int row = wm * 64 + mf * 16 + g;
                a0[mf] = *(const uint2*)&Xs[row * PITCH + kb];
                a1[mf] = *(const uint2*)&Xs[(row + 8) * PITCH + kb];
            }
#pragma unroll
            for (int nf = 0; nf < 4; nf++) {
                int col = wn * 32 + nf * 8 + g;
                bv[nf] = *(const uint2*)&Ws[col * PITCH + kb];
            }
#pragma unroll
            for (int mf = 0; mf < 4; mf++)
#pragma unroll
                for (int nf = 0; nf < 4; nf++)
                    asm volatile(
                        "mma.sync.aligned.m16n8k8.row.col.f32.tf32.tf32.f32 "
                        "{%0,%1,%2,%3}, {%4,%5,%6,%7}, {%8,%9}, {%0,%1,%2,%3};"
                        : "+f"(c[mf][nf][0]), "+f"(c[mf][nf][1]),
                          "+f"(c[mf][nf][2]), "+f"(c[mf][nf][3])
                        : "r"(a0[mf].x), "r"(a1[mf].x), "r"(a0[mf].y), "r"(a1[mf].y),
                          "r"(bv[nf].x), "r"(bv[nf].y));
        }
        __syncthreads();
    }

#pragma unroll
    for (int mf = 0; mf < 4; mf++) {
        int row = m0 + wm * 64 + mf * 16 + g;
#pragma unroll
        for (int nf = 0; nf < 4; nf++) {
            int col = n0 + wn * 32 + nf * 8 + tg * 2;
            float2* p0 = (float2*)(hid + (size_t)row * HIDD + col);
            float2* p1 = (float2*)(hid + (size_t)(row + 8) * HIDD + col);
            *p0 = make_float2(c[mf][nf][0], c[mf][nf][1]);
            *p1 = make_float2(c[mf][nf][2], c[mf][nf][3]);
        }
    }
}

// ---------------------------------------------------------------------------
// Fused: W2 value build (inline) + spmm + hid-tail copy.
//  blockIdx.x < 150 : 64 rows x 64 batches of outp.
//  blockIdx.x == 150: hid[:, 9216:9984] = x for this 64-batch slice.
// Gather reads hid for c < GRIDN, x for c >= GRIDN (passthrough identity).
// ---------------------------------------------------------------------------
__global__ void __launch_bounds__(256)
spmm_fused_kernel(const float* __restrict__ hid, const float* __restrict__ x,
                  const float* __restrict__ Beta, const float* __restrict__ W2f,
                  float* __restrict__ outp, float* __restrict__ hid_tail_dst) {
    const int t  = threadIdx.x;
    const int by = blockIdx.y;           // 0..3, 64 batches each

    if (blockIdx.x == 150) {             // copy block: x -> hid tail
        for (int i = t; i < 64 * 192; i += 256) {
            int b = by * 64 + (i / 192);
            int q = i % 192;
            const float4* src = (const float4*)(x + (size_t)b * INPD);
            float4*       dst = (float4*)(hid_tail_dst + (size_t)b * HIDD + GRIDN);
            dst[q] = src[q];
        }
        return;
    }

    __shared__ int   sc[64 * 5];
    __shared__ float sv[64 * 5];
    const int r0 = blockIdx.x * 64;

    // Phase 0: build this block's 320 (col, val) pairs directly.
    for (int i = t; i < 320; i += 256) {
        int rr = i / 5;
        int k  = i - rr * 5;
        int r  = r0 + rr;
        const float* Br = Beta + (size_t)r * HIDD;
        const float* Fr = W2f  + (size_t)r * HIDD;
        int c; float v;
        if (r < GRIDN) {
            int gi = r / NN, gj = r % NN;
            switch (k) {
            case 0: c = r; v = Fr[r]; break;
            case 1:
                if (gj > 0)      { c = r - 1;             v = Fr[c]; }
                else             { c = GRIDN + 2*NN + gi; v = atanf(Br[c]) + HPI; }
                break;
            case 2:
                if (gj < NN - 1) { c = r + 1;             v = atanf(Br[c]) + HPI; }
                else             { c = GRIDN + 3*NN + gi; v = atanf(Br[c]) + HPI; }
                break;
            case 3:
                if (gi > 0)      { c = r - NN;            v = Fr[c]; }
                else             { c = GRIDN + gj;        v = atanf(Br[c]) + HPI; }
                break;
            default:
                if (gi < NN - 1) { c = r + NN;            v = atanf(Br[c]) + HPI; }
                else             { c = GRIDN + NN + gj;   v = atanf(Br[c]) + HPI; }
                break;
            }
        } else {
            int gg = r - GRIDN;
            int node;
            if      (gg < NN)     node = gg;
            else if (gg < 2 * NN) node = (NN - 1) * NN + (gg - NN);
            else if (gg < 3 * NN) node = (gg - 2 * NN) * NN;
            else                  node = (gg - 3 * NN) * NN + (NN - 1);
            switch (k) {
            case 0:  c = r;         v = Fr[r];         break;
            case 1:  c = node;      v = Fr[node];      break;
            case 2:  c = OUTD + gg; v = Fr[OUTD + gg]; break;
            default: c = 0;         v = 0.0f;          break;
            }
        }
        sc[i] = c;
        sv[i] = v;
    }
    __syncthreads();

    // Phase 1: gather. Thread = (row rr, batch lane bs); 16 batches each.
    const int rr = t & 63;
    const int bs = t >> 6;               // 0..3
    const int r  = r0 + rr;
    const int bb = by * 64 + bs;

    const int c0 = sc[rr*5+0], c1 = sc[rr*5+1], c2 = sc[rr*5+2],
              c3 = sc[rr*5+3], c4 = sc[rr*5+4];
    const float v0 = sv[rr*5+0], v1 = sv[rr*5+1], v2 = sv[rr*5+2],
                v3 = sv[rr*5+3], v4 = sv[rr*5+4];

    // Per-slot base pointer + stride (hid for grid cols, x for ghost cols).
    const float* p0; const float* p1; const float* p2; const float* p3; const float* p4;
    int s0, s1, s2, s3, s4;
    p0 = (c0 < GRIDN) ? hid + (size_t)bb * HIDD + c0 : x + (size_t)bb * INPD + (c0 - GRIDN);
    s0 = (c0 < GRIDN) ? 4 * HIDD : 4 * INPD;
    p1 = (c1 < GRIDN) ? hid + (size_t)bb * HIDD + c1 : x + (size_t)bb * INPD + (c1 - GRIDN);
    s1 = (c1 < GRIDN) ? 4 * HIDD : 4 * INPD;
    p2 = (c2 < GRIDN) ? hid + (size_t)bb * HIDD + c2 : x + (size_t)bb * INPD + (c2 - GRIDN);
    s2 = (c2 < GRIDN) ? 4 * HIDD : 4 * INPD;
    p3 = (c3 < GRIDN) ? hid + (size_t)bb * HIDD + c3 : x + (size_t)bb * INPD + (c3 - GRIDN);
    s3 = (c3 < GRIDN) ? 4 * HIDD : 4 * INPD;
    p4 = (c4 < GRIDN) ? hid + (size_t)bb * HIDD + c4 : x + (size_t)bb * INPD + (c4 - GRIDN);
    s4 = (c4 < GRIDN) ? 4 * HIDD : 4 * INPD;

    float acc[16];
#pragma unroll
    for (int u = 0; u < 16; u++) acc[u]  = v0 * p0[u * s0];
#pragma unroll
    for (int u = 0; u < 16; u++) acc[u] += v1 * p1[u * s1];
#pragma unroll
    for (int u = 0; u < 16; u++) acc[u] += v2 * p2[u * s2];
#pragma unroll
    for (int u = 0; u < 16; u++) acc[u] += v3 * p3[u * s3];
#pragma unroll
    for (int u = 0; u < 16; u++) acc[u] += v4 * p4[u * s4];

    float* ob = outp + (size_t)bb * OUTD + r;
#pragma unroll
    for (int u = 0; u < 16; u++) ob[(size_t)u * 4 * OUTD] = acc[u];
}

// ---------------------------------------------------------------------------
extern "C" void kernel_launch(void* const* d_in, const int* in_sizes, int n_in,
                              void* d_out, int out_size) {
    const float* x    = (const float*)d_in[0];
    const float* W1   = (const float*)d_in[1];
    const float* Beta = (const float*)d_in[4];
    const float* W2f  = (const float*)d_in[5];

    if (out_size < BATCH * OUTD + BATCH * HIDD) return;   // layout guard

    float* outp = (float*)d_out;                          // [256, 9600]
    float* hid  = (float*)d_out + (size_t)BATCH * OUTD;   // [256, 9984]

    dim3 ggrid(GRIDN / 128, BATCH / 128);   // (72, 2)
    gemm_tf32_kernel<<<ggrid, 256>>>(x, W1, hid);

    dim3 sgrid(151, 4);                     // 150 spmm cols + 1 copy col
    spmm_fused_kernel<<<sgrid, 256>>>(hid, x, Beta, W2f, outp, hid);
}